// round 17
// baseline (speedup 1.0000x reference)
#include <cuda_runtime.h>
#include <cuda_bf16.h>
#include <math.h>

// Problem constants (fixed shapes)
#define BB 64      // batch
#define TT 512     // time / bucket_size
#define NU 256     // units
#define N3 768     // 3*units
#define LN_EPS 1e-5f

typedef unsigned long long ull;
typedef unsigned int uint;

// ---------------- scratch (static device arrays; no runtime allocation) ----
__device__ uint2 g_xembp[TT * BB * 128];   // packed bf16 hi/mid, kpair-major
__device__ float g_s1[TT * BB * N3];       // [t][b][768] (LN'd in place)
__device__ uint  g_enc[BB * NU];           // encoded running max for conv
__device__ uint2 g_Wp[128 * N3];           // W packed: 128 kpair x 768
__device__ uint2 g_Kp[384 * NU];           // kern packed: 384 kpair x 256

// ---------------- small helpers -------------------------------------------
__device__ __forceinline__ uint enc_f(float v) {
    uint u = __float_as_uint(v);
    return ((int)u < 0) ? ~u : (u | 0x80000000u);
}
__device__ __forceinline__ float dec_f(uint e) {
    uint u = (e & 0x80000000u) ? (e ^ 0x80000000u) : ~e;
    return __uint_as_float(u);
}
__device__ __forceinline__ float hsig(float v) {
    return fminf(fmaxf(0.2f * v + 0.5f, 0.0f), 1.0f);
}
__device__ __forceinline__ float2 ull2f2(ull v) {
    float2 r;
    asm("mov.b64 {%0, %1}, %2;" : "=f"(r.x), "=f"(r.y) : "l"(v));
    return r;
}
__device__ __forceinline__ ull f22ull(float2 v) {
    ull r;
    asm("mov.b64 %0, {%1, %2};" : "=l"(r) : "f"(v.x), "f"(v.y));
    return r;
}
// raw packed fma: acc.{lo,hi} += a.{lo,hi} * b.{lo,hi}
#define FMA2R(acc, av, bv)                                                 \
    asm("fma.rn.f32x2 %0, %1, %2, %0;" : "+l"(acc) : "l"(av), "l"(bv))

__device__ __forceinline__ uint ctarank() {
    uint r; asm("mov.u32 %0, %%cluster_ctarank;" : "=r"(r)); return r;
}
__device__ __forceinline__ void st_cl_b64(void* laddr, uint r, ull v) {
    uint la = (uint)__cvta_generic_to_shared(laddr);
    asm volatile(
        "{ .reg .b32 ra; mapa.shared::cluster.u32 ra, %0, %1; "
        "st.shared::cluster.b64 [ra], %2; }"
        :: "r"(la), "r"(r), "l"(v) : "memory");
}
#define CLUSTER_SYNC() do {                                        \
    asm volatile("barrier.cluster.arrive.aligned;" ::: "memory");  \
    asm volatile("barrier.cluster.wait.aligned;" ::: "memory");    \
} while (0)

// bf16x3 split: pack two consecutive-k fp32 values into {hiPair, midPair}.
__device__ __forceinline__ uint2 bf16x3_pack(float va, float vb) {
    __nv_bfloat16 ha = __float2bfloat16(va);
    __nv_bfloat16 hb = __float2bfloat16(vb);
    float ra = va - __bfloat162float(ha);
    float rb = vb - __bfloat162float(hb);
    __nv_bfloat16 ma = __float2bfloat16(ra);
    __nv_bfloat16 mb = __float2bfloat16(rb);
    uint hi  = ((uint)__bfloat16_as_ushort(hb) << 16) |
               (uint)__bfloat16_as_ushort(ha);
    uint mid = ((uint)__bfloat16_as_ushort(mb) << 16) |
               (uint)__bfloat16_as_ushort(ma);
    return make_uint2(hi, mid);
}

#define MMA_BF16(cc, a0, a1, a2, a3, b0, b1)                              \
    asm("mma.sync.aligned.m16n8k16.row.col.f32.bf16.bf16.f32 "            \
        "{%0,%1,%2,%3}, {%4,%5,%6,%7}, {%8,%9}, {%0,%1,%2,%3};"           \
        : "+f"(cc[0]), "+f"(cc[1]), "+f"(cc[2]), "+f"(cc[3])              \
        : "r"(a0), "r"(a1), "r"(a2), "r"(a3), "r"(b0), "r"(b1))

// ---------------- embedding gather: packed hi/mid output -------------------
__global__ void embed_kernel(const int* __restrict__ x,
                             const float* __restrict__ emb) {
    int c2 = threadIdx.x;                  // 0..127
    int b = blockIdx.x & 63;
    int t = blockIdx.x >> 6;
    int row = x[(size_t)b * TT + t];
    float2 v = *(const float2*)&emb[(size_t)row * NU + 2 * c2];
    g_xembp[(size_t)blockIdx.x * 128 + c2] = bf16x3_pack(v.x, v.y);
    if (blockIdx.x < 128)
        g_enc[blockIdx.x * 128 + c2] = enc_f(-INFINITY);
}

// ---------------- prep: pack W and kern into kpair-major uint2 -------------
__global__ void prep_kernel(const float* __restrict__ W,
                            const float* __restrict__ kern) {
    int idx = blockIdx.x * 256 + threadIdx.x;
    if (idx < 128 * N3) {
        int kp = idx / N3, n = idx - kp * N3;
        g_Wp[idx] = bf16x3_pack(W[(size_t)(2 * kp) * N3 + n],
                                W[(size_t)(2 * kp + 1) * N3 + n]);
    } else {
        int i = idx - 128 * N3;            // < 384*256
        int kp = i >> 8, n = i & 255;
        g_Kp[i] = bf16x3_pack(kern[(size_t)(2 * kp) * NU + n],
                              kern[(size_t)(2 * kp + 1) * NU + n]);
    }
}

__global__ void decode_kernel(float* __restrict__ out) {
    int f = threadIdx.x;           // 256
    int b = blockIdx.x;            // 64
    out[(size_t)b * 512 + 256 + f] = dec_f(g_enc[b * 256 + f]);
}

// ---------------- 128x128 bf16x3 tensor-core GEMM (R14-proven) -------------
#define AST2 132
#define GTB (8 * AST2)      // uint2 per tile (8 kpair rows x 132)
__global__ void __launch_bounds__(256)
gemm_tc(const uint2* __restrict__ A, const uint2* __restrict__ B,
        const float* __restrict__ bias, float* __restrict__ C,
        int N, int K, int domax) {
    extern __shared__ uint2 dsm2[];
    uint2* As2 = dsm2;               // [2][GTB]
    uint2* Bs2 = dsm2 + 2 * GTB;     // [2][GTB]

    int tid = threadIdx.x;
    int lane = tid & 31, warp = tid >> 5;
    int wm = warp >> 2, wn = warp & 3;           // warp grid 2x4
    int lk = lane & 3, lg = lane >> 2;
    int r0 = blockIdx.y * 128, c0 = blockIdx.x * 128;

    int am = tid >> 1, akp = (tid & 1) * 4;      // A: row am, 4 kpairs
    int bkp = tid >> 5, bn4 = (tid & 31) * 4;    // B: kpair row bkp, 4 n's

    float c[4][4][4];
    #pragma unroll
    for (int i = 0; i < 4; i++)
        #pragma unroll
        for (int j = 0; j < 4; j++)
            #pragma unroll
            for (int q = 0; q < 4; q++) c[i][j][q] = 0.0f;

    const uint2* Arow = A + (size_t)(r0 + am) * 128;

    uint4 aV0, aV1, bV0, bV1;
    {   // prefetch tile 0
        int kp = akp;
        int ab = ((kp >> 7) << 13) + (kp & 127);
        aV0 = *(const uint4*)&Arow[ab];
        aV1 = *(const uint4*)&Arow[ab + 2];
        const uint2* Bp = &B[(size_t)bkp * N + c0 + bn4];
        bV0 = *(const uint4*)Bp;
        bV1 = *(const uint4*)(Bp + 2);
        uint2* as = As2;
        as[(akp + 0) * AST2 + am] = make_uint2(aV0.x, aV0.y);
        as[(akp + 1) * AST2 + am] = make_uint2(aV0.z, aV0.w);
        as[(akp + 2) * AST2 + am] = make_uint2(aV1.x, aV1.y);
        as[(akp + 3) * AST2 + am] = make_uint2(aV1.z, aV1.w);
        *(uint4*)&Bs2[bkp * AST2 + bn4] = bV0;
        *(uint4*)&Bs2[bkp * AST2 + bn4 + 2] = bV1;
    }
    __syncthreads();

    int buf = 0;
    for (int k0 = 0; k0 < K; k0 += 16) {
        bool more = (k0 + 16) < K;
        if (more) {
            int kp = (k0 + 16) / 2 + akp;
            int ab = ((kp >> 7) << 13) + (kp & 127);
            aV0 = *(const uint4*)&Arow[ab];
            aV1 = *(const uint4*)&Arow[ab + 2];
            const uint2* Bp = &B[(size_t)((k0 + 16) / 2 + bkp) * N + c0 + bn4];
            bV0 = *(const uint4*)Bp;
            bV1 = *(const uint4*)(Bp + 2);
        }
        const uint2* as2 = As2 + buf * GTB;
        const uint2* bs2 = Bs2 + buf * GTB;
        {
            uint afH[4][4], afM[4][4], bfH[4][2], bfM[4][2];
            #pragma unroll
            for (int mt = 0; mt < 4; mt++) {
                int m = wm * 64 + mt * 16 + lg;
                int i0 = lk * AST2 + m, i1 = (lk + 4) * AST2 + m;
                uint2 v0 = as2[i0], v1 = as2[i0 + 8];
                uint2 v2 = as2[i1], v3 = as2[i1 + 8];
                afH[mt][0] = v0.x; afM[mt][0] = v0.y;
                afH[mt][1] = v1.x; afM[mt][1] = v1.y;
                afH[mt][2] = v2.x; afM[mt][2] = v2.y;
                afH[mt][3] = v3.x; afM[mt][3] = v3.y;
            }
            #pragma unroll
            for (int nt = 0; nt < 4; nt++) {
                int n = wn * 32 + nt * 8 + lg;
                uint2 w0 = bs2[lk * AST2 + n];
                uint2 w1 = bs2[(lk + 4) * AST2 + n];
                bfH[nt][0] = w0.x; bfM[nt][0] = w0.y;
                bfH[nt][1] = w1.x; bfM[nt][1] = w1.y;
            }
            #pragma unroll
            for (int mt = 0; mt < 4; mt++)
                #pragma unroll
                for (int nt = 0; nt < 4; nt++) {
                    MMA_BF16(c[mt][nt], afM[mt][0], afM[mt][1], afM[mt][2],
                             afM[mt][3], bfH[nt][0], bfH[nt][1]);
                    MMA_BF16(c[mt][nt], afH[mt][0], afH[mt][1], afH[mt][2],
                             afH[mt][3], bfM[nt][0], bfM[nt][1]);
                    MMA_BF16(c[mt][nt], afH[mt][0], afH[mt][1], afH[mt][2],
                             afH[mt][3], bfH[nt][0], bfH[nt][1]);
                }
        }
        if (more) {
            uint2* aT = As2 + (buf ^ 1) * GTB;
            uint2* bT = Bs2 + (buf ^ 1) * GTB;
            aT[(akp + 0) * AST2 + am] = make_uint2(aV0.x, aV0.y);
            aT[(akp + 1) * AST2 + am] = make_uint2(aV0.z, aV0.w);
            aT[(akp + 2) * AST2 + am] = make_uint2(aV1.x, aV1.y);
            aT[(akp + 3) * AST2 + am] = make_uint2(aV1.z, aV1.w);
            *(uint4*)&bT[bkp * AST2 + bn4] = bV0;
            *(uint4*)&bT[bkp * AST2 + bn4 + 2] = bV1;
        }
        __syncthreads();
        buf ^= 1;
    }

    // epilogue
    #pragma unroll
    for (int mt = 0; mt < 4; mt++) {
        #pragma unroll
        for (int nt = 0; nt < 4; nt++) {
            int row0 = r0 + wm * 64 + mt * 16 + lg;
            int col  = c0 + wn * 32 + nt * 8 + lk * 2;
            float v0 = c[mt][nt][0], v1 = c[mt][nt][1];
            float v2 = c[mt][nt][2], v3 = c[mt][nt][3];
            if (bias) {
                float bb0 = bias[col], bb1 = bias[col + 1];
                v0 += bb0; v1 += bb1; v2 += bb0; v3 += bb1;
            }
            if (C) {
                *(float2*)&C[(size_t)row0 * N + col] = make_float2(v0, v1);
                *(float2*)&C[(size_t)(row0 + 8) * N + col] = make_float2(v2, v3);
            }
            if (domax) {
                int ba = row0 & 63, bb = (row0 + 8) & 63;
                atomicMax(&g_enc[ba * 256 + col], enc_f(v0));
                atomicMax(&g_enc[ba * 256 + col + 1], enc_f(v1));
                atomicMax(&g_enc[bb * 256 + col], enc_f(v2));
                atomicMax(&g_enc[bb * 256 + col + 1], enc_f(v3));
            }
        }
    }
}

// ---------------- row LayerNorm over 768 cols, in place on g_s1 ------------
__global__ void ln_kernel(const float* __restrict__ gam,
                          const float* __restrict__ bet) {
    int row = blockIdx.x;
    float* p = g_s1 + (size_t)row * N3;
    int tid = threadIdx.x;
    float v0 = p[tid], v1 = p[tid + 256], v2 = p[tid + 512];
    float s = v0 + v1 + v2;
    float q = v0 * v0 + v1 * v1 + v2 * v2;
    __shared__ float rs[8], rq[8];
    __shared__ float tot[2];
    int lane = tid & 31, w = tid >> 5;
    #pragma unroll
    for (int o = 16; o; o >>= 1) {
        s += __shfl_down_sync(0xffffffffu, s, o);
        q += __shfl_down_sync(0xffffffffu, q, o);
    }
    if (!lane) { rs[w] = s; rq[w] = q; }
    __syncthreads();
    if (tid == 0) {
        float S = 0, Q = 0;
        for (int i = 0; i < 8; i++) { S += rs[i]; Q += rq[i]; }
        tot[0] = S; tot[1] = Q;
    }
    __syncthreads();
    float mean = tot[0] * (1.0f / 768.0f);
    float var = fmaxf(tot[1] * (1.0f / 768.0f) - mean * mean, 0.0f);
    float inv = 1.0f / (sqrtf(var + LN_EPS) + LN_EPS);
    p[tid]       = gam[tid]       * ((v0 - mean) * inv) + bet[tid];
    p[tid + 256] = gam[tid + 256] * ((v1 - mean) * inv) + bet[tid + 256];
    p[tid + 512] = gam[tid + 512] * ((v2 - mean) * inv) + bet[tid + 512];
}

// =============== recurrence: 512 threads/CTA, 2 cluster syncs/step =========
// Phase A: col (tid&127) x k-quarter (tid>>7), UA in regs (32 ull).
// Phase B: col (tid&255) x k-half (tid>>8) of own-rank 64 k, U in SMEM
//   ([kpair][col] layout -> conflict-free). Phase C: tid<256, as R15.
#define REC_SMEM_BYTES (32 * 256 * 8 /*UBs*/ + 640 * 4 /*h,rhl*/ +         \
                        (256 + 1024 + 384 + 256 + 16 + 8) * 8)
__global__ void __launch_bounds__(512, 1) __cluster_dims__(4, 1, 1)
rec_kernel(const int* __restrict__ x, const float* __restrict__ Umat,
           const float* __restrict__ s1, const float* __restrict__ gammas,
           const float* __restrict__ betas, float* __restrict__ out) {
    asm volatile("griddepcontrol.launch_dependents;" ::: "memory");

    extern __shared__ __align__(16) char rsm[];
    ull*    UBs  = (ull*)rsm;                    // [32 kpair][256 col] 64KB
    float*  h0s  = (float*)(UBs + 32 * 256);     // 256
    float*  h1s  = h0s + 256;                    // 256
    float*  rhl0 = h1s + 256;                    // 64
    float*  rhl1 = rhl0 + 64;                    // 64
    float2* z2g  = (float2*)(rhl1 + 64);         // 256
    float2* partHC = z2g + 256;                  // 1024
    float2* cbufA  = partHC + 1024;              // 384 (kq 1..3 partials)
    float2* cbufB  = cbufA + 384;                // 256 (kh=1 partials)
    float2* wsl    = cbufB + 256;                // 16
    float2* pA     = wsl + 16;                   // 8

    int tid  = threadIdx.x;                      // 0..511
    uint rank = ctarank();
    int cid  = blockIdx.x >> 2;
    int b0   = cid * 2, b1 = b0 + 1;
    int lane = tid & 31, wid = tid >> 5;

    int colA = tid & 127;
    int kq4  = tid >> 7;                         // 0..3 k-quarter
    int gA = (colA < 64) ? ((int)rank * 64 + colA)
                         : (256 + (int)rank * 64 + (colA - 64));
    float g1a = gammas[N3 + gA], be1a = betas[N3 + gA];
    int uC = tid & 255;                          // phase-B/C column
    int kh = tid >> 8;                           // 0/1 phase-B k-half
    float g1c = gammas[N3 + 512 + uC], be1c = betas[N3 + 512 + uC];

    // ---- one-time: UA (k-quarter) as packed regs; UB slice into smem ----
    ull UAp[32];
    #pragma unroll
    for (int j = 0; j < 32; j++) {
        float ua = Umat[(size_t)(kq4 * 64 + 2 * j) * N3 + gA];
        float ub = Umat[(size_t)(kq4 * 64 + 2 * j + 1) * N3 + gA];
        UAp[j] = f22ull(make_float2(ua, ub));
    }
    for (int i = tid; i < 32 * 256; i += 512) {
        int kp = i >> 8, c = i & 255;
        float ua = Umat[(size_t)((int)rank * 64 + 2 * kp) * N3 + 512 + c];
        float ub = Umat[(size_t)((int)rank * 64 + 2 * kp + 1) * N3 + 512 + c];
        UBs[i] = f22ull(make_float2(ua, ub));
    }
    if (tid < 256) { h0s[tid] = 0.0f; h1s[tid] = 0.0f; }
    __syncthreads();
    CLUSTER_SYNC();

    for (int t = 0; t < TT; t++) {
        const float* s1r0 = s1 + ((size_t)t * 64 + b0) * N3;
        const float* s1r1 = s1r0 + N3;
        float s1a0 = 0.0f, s1a1 = 0.0f;
        if (tid < 128) { s1a0 = s1r0[gA]; s1a1 = s1r1[gA]; }
        float s1c0 = 0.0f, s1c1 = 0.0f;
        if (tid < 256) { s1c0 = s1r0[512 + uC]; s1c1 = s1r1[512 + uC]; }
        int m0 = x[(size_t)b0 * TT + t], m1 = x[(size_t)b1 * TT + t];

        // ---- phase A: h @ U[:, gA] over k-quarter ----
        const ull* hp0 = (const ull*)h0s + kq4 * 32;
        const ull* hp1 = (const ull*)h1s + kq4 * 32;
        ull a00 = 0, a01 = 0, a10 = 0, a11 = 0;
        #pragma unroll
        for (int j = 0; j < 32; j += 2) {
            ulonglong2 v0 = *(const ulonglong2*)(hp0 + j);
            ulonglong2 v1 = *(const ulonglong2*)(hp1 + j);
            FMA2R(a00, v0.x, UAp[j]); FMA2R(a01, v0.y, UAp[j + 1]);
            FMA2R(a10, v1.x, UAp[j]); FMA2R(a11, v1.y, UAp[j + 1]);
        }
        float2 s00 = ull2f2(a00), s01 = ull2f2(a01);
        float2 s10 = ull2f2(a10), s11 = ull2f2(a11);
        float2 accA = make_float2((s00.x + s00.y) + (s01.x + s01.y),
                                  (s10.x + s10.y) + (s11.x + s11.y));
        if (kq4 > 0) cbufA[(kq4 - 1) * 128 + colA] = accA;
        __syncthreads();

        float2 sval = make_float2(0.0f, 0.0f);
        if (tid < 128) {
            float2 o1 = cbufA[colA], o2 = cbufA[128 + colA];
            float2 o3 = cbufA[256 + colA];
            sval.x = accA.x + o1.x + o2.x + o3.x;
            sval.y = accA.y + o1.y + o2.y + o3.y;
            float p0 = sval.x, p1 = sval.y;
            float q0 = p0 * p0, q1 = p1 * p1;
            #pragma unroll
            for (int o = 16; o; o >>= 1) {
                p0 += __shfl_down_sync(0xffffffffu, p0, o);
                p1 += __shfl_down_sync(0xffffffffu, p1, o);
                q0 += __shfl_down_sync(0xffffffffu, q0, o);
                q1 += __shfl_down_sync(0xffffffffu, q1, o);
            }
            if (!lane) { wsl[wid] = make_float2(p0, p1);
                         wsl[8 + wid] = make_float2(q0, q1); }
        }
        __syncthreads();
        if (tid == 0) {
            float2 S = make_float2(0, 0), Q = make_float2(0, 0);
            #pragma unroll
            for (int w = 0; w < 4; w++) {
                S.x += wsl[w].x; S.y += wsl[w].y;
                Q.x += wsl[8 + w].x; Q.y += wsl[8 + w].y;
            }
            #pragma unroll
            for (uint r = 0; r < 4; r++) {
                st_cl_b64(&pA[rank], r, f22ull(S));
                st_cl_b64(&pA[4 + rank], r, f22ull(Q));
            }
        }
        CLUSTER_SYNC();   // S1: LN-A partials visible everywhere

        // ---- gate: z broadcast; rh LOCAL ----
        if (tid < 128) {
            float2 S = make_float2(0, 0), Q = make_float2(0, 0);
            #pragma unroll
            for (int r = 0; r < 4; r++) {
                S.x += pA[r].x; S.y += pA[r].y;
                Q.x += pA[4 + r].x; Q.y += pA[4 + r].y;
            }
            float mean0 = S.x * (1.0f / 512.0f), mean1 = S.y * (1.0f / 512.0f);
            float var0 = fmaxf(Q.x * (1.0f / 512.0f) - mean0 * mean0, 0.0f);
            float var1 = fmaxf(Q.y * (1.0f / 512.0f) - mean1 * mean1, 0.0f);
            float inv0 = 1.0f / (sqrtf(var0 + LN_EPS) + LN_EPS);
            float inv1 = 1.0f / (sqrtf(var1 + LN_EPS) + LN_EPS);
            float sv0 = hsig(s1a0 + g1a * ((sval.x - mean0) * inv0) + be1a);
            float sv1 = hsig(s1a1 + g1a * ((sval.y - mean1) * inv1) + be1a);
            if (colA < 64) {
                int gz = (int)rank * 64 + colA;
                ull pv = f22ull(make_float2(sv0, sv1));
                #pragma unroll
                for (uint r = 0; r < 4; r++) st_cl_b64(&z2g[gz], r, pv);
            } else {
                int uu = colA - 64;
                int gu = (int)rank * 64 + uu;
                rhl0[uu] = sv0 * h0s[gu];
                rhl1[uu] = sv1 * h1s[gu];
            }
        }
        __syncthreads();   // rhl ready (local)

        // ---- phase B: partial (own rh slice, k-half kh) @ UBs[:, uC] ----
        {
            const ull* rp0 = (const ull*)rhl0 + kh * 16;
            const ull* rp1 = (const ull*)rhl1 + kh * 16;
            const ull* ub = UBs + (kh * 16) * 256 + uC;
            ull b00 = 0, b01 = 0, b10 = 0, b11 = 0;
            #pragma unroll
            for (int j = 0; j < 16; j += 2) {
                ulonglong2 v0 = *(const ulonglong2*)(rp0 + j);
                ulonglong2 v1 = *(const ulonglong2*)(rp1 + j);
                ull u0 = ub[j * 256], u1 = ub[(j + 1) * 256];
                FMA2R(b00, v0.x, u0); FMA2R(b01, v0.y, u1);
                FMA2R(b10, v1.x, u0); FMA2R(b11, v1.y, u1);
            }
            float2 t00 = ull2f2(b00), t01 = ull2f2(b01);
            float2 t10 = ull2f2(b10), t11 = ull2f2(b11);
            float2 part = make_float2((t00.x + t00.y) + (t01.x + t01.y),
                                      (t10.x + t10.y) + (t11.x + t11.y));
            if (kh == 1) {
                cbufB[uC] = part;
            } else {
                // stash own half; combined after sync below
                cbufA[uC].x = part.x; cbufA[uC].y = part.y;
            }
        }
        __syncthreads();
        if (tid < 256) {
            float2 own = cbufA[uC], oth = cbufB[uC];
            float2 part = make_float2(own.x + oth.x, own.y + oth.y);
            ull pv = f22ull(part);
            #pragma unroll
            for (uint r = 0; r < 4; r++)
                st_cl_b64(&partHC[(int)rank * 256 + uC], r, pv);
        }
        CLUSTER_SYNC();   // S2: hc partials + z visible everywhere

        // ---- phase C: sum partials, LOCAL LN-B, gated update (tid<256) ---
        if (tid < 256) {
            float2 p0v = partHC[uC],        p1v = partHC[256 + uC];
            float2 p2v = partHC[512 + uC],  p3v = partHC[768 + uC];
            float2 sB = make_float2((p0v.x + p1v.x) + (p2v.x + p3v.x),
                                    (p0v.y + p1v.y) + (p2v.y + p3v.y));
            float p0 = sB.x, p1 = sB.y, q0 = p0 * p0, q1 = p1 * p1;
            #pragma unroll
            for (int o = 16; o; o >>= 1) {
                p0 += __shfl_down_sync(0xffffffffu, p0, o);
                p1 += __shfl_down_sync(0xffffffffu, p1, o);
                q0 += __shfl_down_sync(0xffffffffu, q0, o);
                q1 += __shfl_down_sync(0xffffffffu, q1, o);
            }
            if (!lane) { wsl[wid] = make_float2(p0, p1);
                         wsl[8 + wid] = make_float2(q0, q1); }
            __syncthreads();
            float2 S = make_float2(0, 0), Q = make_float2(0, 0);
            #pragma unroll
            for (int w = 0; w < 8; w++) {
                S.x += wsl[w].x; S.y += wsl[w].y;
                Q.x += wsl[8 + w].x; Q.y += wsl[8 + w].y;
            }
            float mean0 = S.x * (1.0f / 256.0f), mean1 = S.y * (1.0f / 256.0f);
            float var0 = fmaxf(Q.x * (1.0f / 256.0f) - mean0 * mean0, 0.0f);
            float var1 = fmaxf(Q.y * (1.0f / 256.0f) - mean1 * mean1, 0.0f);
            float inv0 = 1.0f / (sqrtf(var0 + LN_EPS) + LN_EPS);
            float inv1 = 1.0f / (sqrtf(var1 + LN_EPS) + LN_EPS);
            float hc0 = tanhf(s1c0 + g1c * ((sB.x - mean0) * inv0) + be1c);
            float hc1 = tanhf(s1c1 + g1c * ((sB.y - mean1) * inv1) + be1c);
            float2 z = z2g[uC];
            float h0 = h0s[uC], h1 = h1s[uC];
            float hn0 = z.x * h0 + (1.0f - z.x) * hc0;
            float hn1 = z.y * h1 + (1.0f - z.y) * hc1;
            h0s[uC] = m0 ? hn0 : h0;
            h1s[uC] = m1 ? hn1 : h1;
        } else {
            __syncthreads();   // matching barrier for tid>=256
        }
        __syncthreads();   // h complete before next phase A (CTA-local)
    }

    if (rank == 0 && tid < 256) {
        out[(size_t)b0 * 512 + uC] = h0s[uC];
        out[(size_t)b1 * 512 + uC] = h1s[uC];
    }
}

// ---------------- launch ---------------------------------------------------
extern "C" void kernel_launch(void* const* d_in, const int* in_sizes, int n_in,
                              void* d_out, int out_size) {
    const int* x           = (const int*)d_in[0];   // token ids (int32)
    const float* emb       = (const float*)d_in[2];
    const float* W         = (const float*)d_in[3];
    const float* Umat      = (const float*)d_in[4];
    const float* bias      = (const float*)d_in[5];
    const float* gammas    = (const float*)d_in[6];
    const float* betas     = (const float*)d_in[7];
    const float* kern      = (const float*)d_in[8];
    float* out             = (float*)d_out;

    uint2 *xep, *Wp, *Kp;
    float *s1p;
    cudaGetSymbolAddress((void**)&xep, g_xembp);
    cudaGetSymbolAddress((void**)&Wp, g_Wp);
    cudaGetSymbolAddress((void**)&Kp, g_Kp);
    cudaGetSymbolAddress((void**)&s1p, g_s1);

    const int gsm = 4 * GTB * (int)sizeof(uint2);   // 33792 B
    cudaFuncSetAttribute(gemm_tc, cudaFuncAttributeMaxDynamicSharedMemorySize,
                         gsm);
    cudaFuncSetAttribute(rec_kernel,
                         cudaFuncAttributeMaxDynamicSharedMemorySize,
                         REC_SMEM_BYTES);

    // 1) embedding gather (packed) + weight packing + g_enc init
    embed_kernel<<<TT * BB, 128>>>(x, emb);
    prep_kernel<<<768, 256>>>(W, kern);
    // 2) s1 = x_emb @ W + b, then LN in place
    gemm_tc<<<dim3(N3 / 128, TT * BB / 128), 256, gsm>>>(xep, Wp, bias, s1p,
                                                         N3, NU, 0);
    ln_kernel<<<TT * BB, 256>>>(gammas, betas);
    // 3) recurrence (fires griddepcontrol.launch_dependents at entry)
    rec_kernel<<<128, 512, REC_SMEM_BYTES>>>(x, Umat, s1p, gammas, betas, out);
    // 4) conv GEMM as PDL dependent of rec (runs in rec's shadow)
    {
        cudaLaunchConfig_t cfg = {};
        cfg.gridDim = dim3(NU / 128, (510 * BB) / 128);
        cfg.blockDim = dim3(256);
        cfg.dynamicSmemBytes = gsm;
        cfg.stream = 0;
        cudaLaunchAttribute at[1];
        at[0].id = cudaLaunchAttributeProgrammaticStreamSerialization;
        at[0].val.programmaticStreamSerializationAllowed = 1;
        cfg.attrs = at;
        cfg.numAttrs = 1;
        cudaLaunchKernelEx(&cfg, gemm_tc, (const uint2*)xep,
                           (const uint2*)Kp, (const float*)nullptr,
                           (float*)nullptr, (int)NU, (int)(3 * NU), 1);
    }
    // 5) decode (normal full-completion edge after conv)
    decode_kernel<<<BB, 256>>>(out);
}